// round 4
// baseline (speedup 1.0000x reference)
#include <cuda_runtime.h>
#include <cuda_bf16.h>
#include <cstdint>
#include <float.h>

// Problem constants (RaggedTopKGatingModule: N=524288, E=64, K=8)
#define E_EXPERTS 64
#define TOPK 8
#define BLOCK_A 256
#define TOK_PER_BLOCK BLOCK_A                          // 256
#define SLOTS_PER_CHUNK (TOK_PER_BLOCK * TOPK)         // 2048
#define ROUNDS (SLOTS_PER_CHUNK / BLOCK_A)             // 8
#define MAX_SLOTS (524288 * 8)
#define MAX_CHUNKS 2048

// Scratch (no allocation allowed; __device__ globals)
__device__ uint8_t  g_eids[MAX_SLOTS];        // 4 MB   expert id per slot
__device__ uint16_t g_lrank[MAX_SLOTS];       // 8 MB   within-chunk rank
__device__ int      g_chunk_hist[MAX_CHUNKS * E_EXPERTS];
__device__ int      g_chunk_base[MAX_CHUNKS * E_EXPERTS];

// float -> order-preserving uint32 (monotonic)
__device__ __forceinline__ unsigned f2key(float x) {
    unsigned b = __float_as_uint(x);
    return (b & 0x80000000u) ? ~b : (b | 0x80000000u);
}
__device__ __forceinline__ float key2f(unsigned u) {
    unsigned b = (u & 0x80000000u) ? (u & 0x7fffffffu) : ~u;
    return __uint_as_float(b);
}

// ---------------------------------------------------------------------------
// Kernel A: top-8 (lossless 64-bit keys) + softmax + logits copy + ranking
// ---------------------------------------------------------------------------
__global__ __launch_bounds__(BLOCK_A, 6)
void topk_rank_kernel(const float* __restrict__ logits,
                      float* __restrict__ out_scores,
                      float* __restrict__ out_assign,
                      float* __restrict__ out_logits,
                      int n_tokens)
{
    __shared__ uint8_t sh_e[SLOTS_PER_CHUNK];       // 2 KB
    __shared__ int sh_wh[8 * E_EXPERTS];            // 2 KB per-warp hist
    __shared__ int sh_running[E_EXPERTS];           // 256 B

    const int tid  = threadIdx.x;
    const int lane = tid & 31;
    const int warp = tid >> 5;
    const int chunk = blockIdx.x;
    const int tok_base = chunk * TOK_PER_BLOCK;

    // -------- Phase 0: coalesced pass-through copy (warms L1) --------
    {
        const size_t base = (size_t)tok_base * E_EXPERTS;
        const float4* src = (const float4*)(logits + base);
        float4*       dst = (float4*)(out_logits + base);
        const int n4 = TOK_PER_BLOCK * E_EXPERTS / 4;   // 4096 float4
        #pragma unroll
        for (int i = tid; i < n4; i += BLOCK_A)
            dst[i] = src[i];
    }

    // -------- Phase 1: per-token top-8 + softmax --------
    {
        const int t = tok_base + tid;
        const float4* row = (const float4*)(logits + (size_t)t * E_EXPERTS);

        unsigned long long tv[TOPK];
        #pragma unroll
        for (int k = 0; k < TOPK; ++k) tv[k] = 0ull;

        float s0 = 0.f, s1 = 0.f, s2 = 0.f, s3 = 0.f;

        #pragma unroll
        for (int j = 0; j < E_EXPERTS / 4; ++j) {
            float4 q = row[j];
            float xs[4] = {q.x, q.y, q.z, q.w};
            s0 += __expf(q.x); s1 += __expf(q.y);
            s2 += __expf(q.z); s3 += __expf(q.w);
            #pragma unroll
            for (int u = 0; u < 4; ++u) {
                const unsigned e = j * 4 + u;
                // lossless key: high 32 = monotone float bits, low 6 = 63-e
                unsigned long long key =
                    ((unsigned long long)f2key(xs[u]) << 32) | (63u - e);
                if (key > tv[TOPK - 1]) {
                    tv[TOPK - 1] = key;
                    #pragma unroll
                    for (int jj = TOPK - 1; jj > 0; --jj) {
                        if (tv[jj] > tv[jj - 1]) {
                            unsigned long long tt = tv[jj];
                            tv[jj] = tv[jj - 1]; tv[jj - 1] = tt;
                        }
                    }
                }
            }
        }

        const float inv = 1.0f / ((s0 + s1) + (s2 + s3));
        float sc[TOPK];
        #pragma unroll
        for (int k = 0; k < TOPK; ++k) {
            sc[k] = __expf(key2f((unsigned)(tv[k] >> 32))) * inv;
            sh_e[tid * TOPK + k] = (uint8_t)(63u - ((unsigned)tv[k] & 63u));
        }
        float4* srow = (float4*)(out_scores + (size_t)t * TOPK);
        srow[0] = make_float4(sc[0], sc[1], sc[2], sc[3]);
        srow[1] = make_float4(sc[4], sc[5], sc[6], sc[7]);
    }

    // init for ranking phase
    if (tid < E_EXPERTS) sh_running[tid] = 0;
    sh_wh[tid] = 0; sh_wh[tid + BLOCK_A] = 0;
    __syncthreads();

    // -------- Phase 2: ordered multisplit ranking over 2048 slots --------
    const size_t slot_base = (size_t)chunk * SLOTS_PER_CHUNK;
    for (int r = 0; r < ROUNDS; ++r) {
        const int slot = r * BLOCK_A + tid;         // token-major slot order
        const int e = sh_e[slot];

        unsigned mask = __match_any_sync(0xffffffffu, e);
        const int lrank = __popc(mask & ((1u << lane) - 1));
        const int leader = __ffs(mask) - 1;
        if (lane == leader) sh_wh[warp * E_EXPERTS + e] = __popc(mask);
        __syncthreads();

        int base = sh_running[e];
        #pragma unroll
        for (int w = 0; w < 8; ++w)
            if (w < warp) base += sh_wh[w * E_EXPERTS + e];
        const int rank = base + lrank;

        const size_t gslot = slot_base + slot;
        g_lrank[gslot] = (uint16_t)rank;
        g_eids[gslot]  = (uint8_t)e;
        out_assign[gslot] = (float)e;

        int addv = 0;
        if (tid < E_EXPERTS) {
            #pragma unroll
            for (int w = 0; w < 8; ++w) addv += sh_wh[w * E_EXPERTS + tid];
        }
        __syncthreads();                            // all reads of wh/running done
        if (tid < E_EXPERTS) sh_running[tid] += addv;
        sh_wh[tid] = 0; sh_wh[tid + BLOCK_A] = 0;   // zero for next round
        __syncthreads();
    }

    if (tid < E_EXPERTS)
        g_chunk_hist[chunk * E_EXPERTS + tid] = sh_running[tid];
}

// ---------------------------------------------------------------------------
// Kernel B: per-expert exclusive scan over 2048 chunk histograms (2 per thread)
// ---------------------------------------------------------------------------
__global__ void scan_kernel(float* __restrict__ out_counts, int n_chunks)
{
    __shared__ int s[1024];
    const int e = blockIdx.x;
    const int c = threadIdx.x;

    const int c0 = 2 * c, c1 = 2 * c + 1;
    int a = (c0 < n_chunks) ? g_chunk_hist[c0 * E_EXPERTS + e] : 0;
    int b = (c1 < n_chunks) ? g_chunk_hist[c1 * E_EXPERTS + e] : 0;
    int pair = a + b;
    s[c] = pair;
    __syncthreads();

    #pragma unroll
    for (int off = 1; off < 1024; off <<= 1) {
        int t = (c >= off) ? s[c - off] : 0;
        __syncthreads();
        s[c] += t;
        __syncthreads();
    }
    const int incl = s[c];
    const int excl = incl - pair;
    if (c0 < n_chunks) g_chunk_base[c0 * E_EXPERTS + e] = excl;
    if (c1 < n_chunks) g_chunk_base[c1 * E_EXPERTS + e] = excl + a;
    if (c == 1023) out_counts[e] = (float)incl;
}

// ---------------------------------------------------------------------------
// Kernel C: final offsets = chunk_base + local rank  (4 slots / thread)
// ---------------------------------------------------------------------------
__global__ __launch_bounds__(256, 8)
void offsets_kernel(float* __restrict__ out_offs, int n_quads)
{
    const int q = blockIdx.x * blockDim.x + threadIdx.x;
    if (q >= n_quads) return;
    const int idx = q * 4;
    const int chunk = idx >> 11;                    // / SLOTS_PER_CHUNK

    uchar4  e4 = *(const uchar4*)(g_eids + idx);
    ushort4 r4 = *(const ushort4*)(g_lrank + idx);
    const int* base = g_chunk_base + chunk * E_EXPERTS;

    float4 o;
    o.x = (float)(base[e4.x] + r4.x);
    o.y = (float)(base[e4.y] + r4.y);
    o.z = (float)(base[e4.z] + r4.z);
    o.w = (float)(base[e4.w] + r4.w);
    *(float4*)(out_offs + idx) = o;
}

// ---------------------------------------------------------------------------
extern "C" void kernel_launch(void* const* d_in, const int* in_sizes, int n_in,
                              void* d_out, int out_size)
{
    // inputs: [0]=expert_counts(E), [1]=assignments(N*K), [2]=offsets(N*K), [3]=logits(N*E)
    const float* logits = (const float*)d_in[3];
    const int n_tokens = in_sizes[3] / E_EXPERTS;       // 524288
    const int n_slots  = n_tokens * TOPK;               // 4194304
    const int n_chunks = n_tokens / TOK_PER_BLOCK;      // 2048

    float* out = (float*)d_out;
    // layout: counts[E] | scores[N*K] | assign[N*K] | offs[N*K] | logits[N*E]
    float* out_counts = out;
    float* out_scores = out + E_EXPERTS;
    float* out_assign = out_scores + (size_t)n_slots;
    float* out_offs   = out_assign + (size_t)n_slots;
    float* out_logits = out_offs   + (size_t)n_slots;

    topk_rank_kernel<<<n_chunks, BLOCK_A>>>(logits, out_scores, out_assign,
                                            out_logits, n_tokens);
    scan_kernel<<<E_EXPERTS, 1024>>>(out_counts, n_chunks);
    const int n_quads = n_slots / 4;
    offsets_kernel<<<(n_quads + 255) / 256, 256>>>(out_offs, n_quads);
}

// round 5
// speedup vs baseline: 1.1845x; 1.1845x over previous
#include <cuda_runtime.h>
#include <cuda_bf16.h>
#include <cstdint>
#include <float.h>

// Problem constants (RaggedTopKGatingModule: N=524288, E=64, K=8)
#define E_EXPERTS 64
#define TOPK 8
#define BLOCK_A 256
#define TOK_PER_BLOCK BLOCK_A                          // 256
#define SLOTS_PER_CHUNK (TOK_PER_BLOCK * TOPK)         // 2048
#define ROUNDS (SLOTS_PER_CHUNK / BLOCK_A)             // 8
#define MAX_SLOTS (524288 * 8)
#define MAX_CHUNKS 2048

// Scratch (no allocation allowed; __device__ globals)
// packed per-slot: (expert_id << 8) | within_chunk_rank   (rank <= 255)
__device__ uint16_t g_pack[MAX_SLOTS];                 // 8 MB
__device__ int      g_chunk_hist[MAX_CHUNKS * E_EXPERTS];
__device__ int      g_chunk_base[MAX_CHUNKS * E_EXPERTS];

// ---------------------------------------------------------------------------
// Kernel A: top-8 (exact 32-bit sort) + softmax (no max-sub) + logits copy
//           + ordered in-chunk ranking
// ---------------------------------------------------------------------------
__global__ __launch_bounds__(BLOCK_A, 6)
void topk_rank_kernel(const float* __restrict__ logits,
                      float* __restrict__ out_scores,
                      float* __restrict__ out_assign,
                      float* __restrict__ out_logits,
                      int n_tokens)
{
    __shared__ uint8_t sh_e[SLOTS_PER_CHUNK];       // 2 KB
    __shared__ int sh_wh[8 * E_EXPERTS];            // 2 KB per-warp hist
    __shared__ int sh_running[E_EXPERTS];           // 256 B

    const int tid  = threadIdx.x;
    const int lane = tid & 31;
    const int warp = tid >> 5;
    const int chunk = blockIdx.x;
    const int tok_base = chunk * TOK_PER_BLOCK;

    // -------- Phase 0: coalesced pass-through copy (warms L1) --------
    {
        const size_t base = (size_t)tok_base * E_EXPERTS;
        const float4* src = (const float4*)(logits + base);
        float4*       dst = (float4*)(out_logits + base);
        const int n4 = TOK_PER_BLOCK * E_EXPERTS / 4;   // 4096 float4
        #pragma unroll
        for (int i = tid; i < n4; i += BLOCK_A)
            dst[i] = src[i];
    }

    // -------- Phase 1: per-token exact top-8 + softmax (no max subtraction) --
    {
        const int t = tok_base + tid;
        const float4* row = (const float4*)(logits + (size_t)t * E_EXPERTS);

        float tv[TOPK];
        int   ti[TOPK];
        #pragma unroll
        for (int k = 0; k < TOPK; ++k) { tv[k] = -FLT_MAX; ti[k] = 0; }

        float s0 = 0.f, s1 = 0.f, s2 = 0.f, s3 = 0.f;

        #pragma unroll
        for (int j = 0; j < E_EXPERTS / 4; ++j) {
            float4 q = row[j];
            float xs[4] = {q.x, q.y, q.z, q.w};
            s0 += __expf(q.x); s1 += __expf(q.y);
            s2 += __expf(q.z); s3 += __expf(q.w);
            #pragma unroll
            for (int u = 0; u < 4; ++u) {
                const int e = j * 4 + u;
                const float x = xs[u];
                // strict > everywhere: lowest-index-first on exact ties
                if (x > tv[TOPK - 1]) {
                    tv[TOPK - 1] = x; ti[TOPK - 1] = e;
                    #pragma unroll
                    for (int jj = TOPK - 1; jj > 0; --jj) {
                        if (tv[jj] > tv[jj - 1]) {
                            float tf = tv[jj]; tv[jj] = tv[jj - 1]; tv[jj - 1] = tf;
                            int   tt = ti[jj]; ti[jj] = ti[jj - 1]; ti[jj - 1] = tt;
                        }
                    }
                }
            }
        }

        const float inv = 1.0f / ((s0 + s1) + (s2 + s3));
        float sc[TOPK];
        #pragma unroll
        for (int k = 0; k < TOPK; ++k) {
            sc[k] = __expf(tv[k]) * inv;
            sh_e[tid * TOPK + k] = (uint8_t)ti[k];
        }
        float4* srow = (float4*)(out_scores + (size_t)t * TOPK);
        srow[0] = make_float4(sc[0], sc[1], sc[2], sc[3]);
        srow[1] = make_float4(sc[4], sc[5], sc[6], sc[7]);
    }

    // init for ranking phase
    if (tid < E_EXPERTS) sh_running[tid] = 0;
    sh_wh[tid] = 0; sh_wh[tid + BLOCK_A] = 0;
    __syncthreads();

    // -------- Phase 2: ordered multisplit ranking over 2048 slots --------
    const size_t slot_base = (size_t)chunk * SLOTS_PER_CHUNK;
    for (int r = 0; r < ROUNDS; ++r) {
        const int slot = r * BLOCK_A + tid;         // token-major slot order
        const int e = sh_e[slot];

        unsigned mask = __match_any_sync(0xffffffffu, e);
        const int lrank = __popc(mask & ((1u << lane) - 1));
        const int leader = __ffs(mask) - 1;
        if (lane == leader) sh_wh[warp * E_EXPERTS + e] = __popc(mask);
        __syncthreads();

        int base = sh_running[e];
        #pragma unroll
        for (int w = 0; w < 8; ++w)
            if (w < warp) base += sh_wh[w * E_EXPERTS + e];
        const int rank = base + lrank;              // < 256 (distinct experts/token)

        const size_t gslot = slot_base + slot;
        g_pack[gslot] = (uint16_t)((e << 8) | rank);
        out_assign[gslot] = (float)e;

        int addv = 0;
        if (tid < E_EXPERTS) {
            #pragma unroll
            for (int w = 0; w < 8; ++w) addv += sh_wh[w * E_EXPERTS + tid];
        }
        __syncthreads();                            // all reads of wh/running done
        if (tid < E_EXPERTS) sh_running[tid] += addv;
        sh_wh[tid] = 0; sh_wh[tid + BLOCK_A] = 0;   // zero for next round
        __syncthreads();
    }

    if (tid < E_EXPERTS)
        g_chunk_hist[chunk * E_EXPERTS + tid] = sh_running[tid];
}

// ---------------------------------------------------------------------------
// Kernel B: per-expert exclusive scan over 2048 chunk histograms (2 per thread)
// ---------------------------------------------------------------------------
__global__ void scan_kernel(float* __restrict__ out_counts, int n_chunks)
{
    __shared__ int s[1024];
    const int e = blockIdx.x;
    const int c = threadIdx.x;

    const int c0 = 2 * c, c1 = 2 * c + 1;
    int a = (c0 < n_chunks) ? g_chunk_hist[c0 * E_EXPERTS + e] : 0;
    int b = (c1 < n_chunks) ? g_chunk_hist[c1 * E_EXPERTS + e] : 0;
    int pair = a + b;
    s[c] = pair;
    __syncthreads();

    #pragma unroll
    for (int off = 1; off < 1024; off <<= 1) {
        int t = (c >= off) ? s[c - off] : 0;
        __syncthreads();
        s[c] += t;
        __syncthreads();
    }
    const int incl = s[c];
    const int excl = incl - pair;
    if (c0 < n_chunks) g_chunk_base[c0 * E_EXPERTS + e] = excl;
    if (c1 < n_chunks) g_chunk_base[c1 * E_EXPERTS + e] = excl + a;
    if (c == 1023) out_counts[e] = (float)incl;
}

// ---------------------------------------------------------------------------
// Kernel C: final offsets = chunk_base + local rank  (4 slots / thread)
// ---------------------------------------------------------------------------
__global__ __launch_bounds__(256, 8)
void offsets_kernel(float* __restrict__ out_offs, int n_quads)
{
    const int q = blockIdx.x * blockDim.x + threadIdx.x;
    if (q >= n_quads) return;
    const int idx = q * 4;
    const int chunk = idx >> 11;                    // / SLOTS_PER_CHUNK

    ushort4 p4 = *(const ushort4*)(g_pack + idx);
    const int* base = g_chunk_base + chunk * E_EXPERTS;

    float4 o;
    o.x = (float)(base[p4.x >> 8] + (p4.x & 255));
    o.y = (float)(base[p4.y >> 8] + (p4.y & 255));
    o.z = (float)(base[p4.z >> 8] + (p4.z & 255));
    o.w = (float)(base[p4.w >> 8] + (p4.w & 255));
    *(float4*)(out_offs + idx) = o;
}

// ---------------------------------------------------------------------------
extern "C" void kernel_launch(void* const* d_in, const int* in_sizes, int n_in,
                              void* d_out, int out_size)
{
    // inputs: [0]=expert_counts(E), [1]=assignments(N*K), [2]=offsets(N*K), [3]=logits(N*E)
    const float* logits = (const float*)d_in[3];
    const int n_tokens = in_sizes[3] / E_EXPERTS;       // 524288
    const int n_slots  = n_tokens * TOPK;               // 4194304
    const int n_chunks = n_tokens / TOK_PER_BLOCK;      // 2048

    float* out = (float*)d_out;
    // layout: counts[E] | scores[N*K] | assign[N*K] | offs[N*K] | logits[N*E]
    float* out_counts = out;
    float* out_scores = out + E_EXPERTS;
    float* out_assign = out_scores + (size_t)n_slots;
    float* out_offs   = out_assign + (size_t)n_slots;
    float* out_logits = out_offs   + (size_t)n_slots;

    topk_rank_kernel<<<n_chunks, BLOCK_A>>>(logits, out_scores, out_assign,
                                            out_logits, n_tokens);
    scan_kernel<<<E_EXPERTS, 1024>>>(out_counts, n_chunks);
    const int n_quads = n_slots / 4;
    offsets_kernel<<<(n_quads + 255) / 256, 256>>>(out_offs, n_quads);
}

// round 6
// speedup vs baseline: 1.2099x; 1.0215x over previous
#include <cuda_runtime.h>
#include <cuda_bf16.h>
#include <cstdint>
#include <float.h>

// Problem constants (RaggedTopKGatingModule: N=524288, E=64, K=8)
#define E_EXPERTS 64
#define TOPK 8
#define BLOCK_A 256
#define TOK_PER_BLOCK BLOCK_A                          // 256
#define SLOTS_PER_CHUNK (TOK_PER_BLOCK * TOPK)         // 2048
#define ROUNDS (SLOTS_PER_CHUNK / BLOCK_A)             // 8
#define MAX_SLOTS (524288 * 8)
#define MAX_CHUNKS 2048

// Scratch (no allocation allowed; __device__ globals)
// packed per-slot: (expert_id << 8) | within_chunk_rank   (rank <= 255)
__device__ uint16_t g_pack[MAX_SLOTS];                 // 8 MB
__device__ int      g_chunk_hist[MAX_CHUNKS * E_EXPERTS];
__device__ int      g_chunk_base[MAX_CHUNKS * E_EXPERTS];

// ---------------------------------------------------------------------------
// Kernel A: top-8 (exact 32-bit sort) + softmax (no max-sub) + logits copy
//           + ordered in-chunk ranking (hoisted cross-warp scan)
// ---------------------------------------------------------------------------
__global__ __launch_bounds__(BLOCK_A, 6)
void topk_rank_kernel(const float* __restrict__ logits,
                      float* __restrict__ out_scores,
                      float* __restrict__ out_logits,
                      int n_tokens)
{
    __shared__ uint8_t sh_e[SLOTS_PER_CHUNK];       // 2 KB
    __shared__ int sh_wh[8 * E_EXPERTS];            // 2 KB per-warp hist
    __shared__ int sh_base[8 * E_EXPERTS];          // 2 KB scanned bases
    __shared__ int sh_running[E_EXPERTS];           // 256 B

    const int tid  = threadIdx.x;
    const int lane = tid & 31;
    const int warp = tid >> 5;
    const int chunk = blockIdx.x;
    const int tok_base = chunk * TOK_PER_BLOCK;

    // -------- Phase 0: coalesced pass-through copy (warms caches) --------
    {
        const size_t base = (size_t)tok_base * E_EXPERTS;
        const float4* src = (const float4*)(logits + base);
        float4*       dst = (float4*)(out_logits + base);
        const int n4 = TOK_PER_BLOCK * E_EXPERTS / 4;   // 4096 float4
        #pragma unroll
        for (int i = tid; i < n4; i += BLOCK_A)
            dst[i] = src[i];
    }

    // -------- Phase 1: per-token exact top-8 + softmax (no max subtraction) --
    {
        const int t = tok_base + tid;
        const float4* row = (const float4*)(logits + (size_t)t * E_EXPERTS);

        float tv[TOPK];
        int   ti[TOPK];
        #pragma unroll
        for (int k = 0; k < TOPK; ++k) { tv[k] = -FLT_MAX; ti[k] = 0; }

        float s0 = 0.f, s1 = 0.f, s2 = 0.f, s3 = 0.f;

        #pragma unroll
        for (int j = 0; j < E_EXPERTS / 4; ++j) {
            float4 q = row[j];
            float xs[4] = {q.x, q.y, q.z, q.w};
            s0 += __expf(q.x); s1 += __expf(q.y);
            s2 += __expf(q.z); s3 += __expf(q.w);
            #pragma unroll
            for (int u = 0; u < 4; ++u) {
                const int e = j * 4 + u;
                const float x = xs[u];
                // strict > everywhere: lowest-index-first on exact ties
                if (x > tv[TOPK - 1]) {
                    tv[TOPK - 1] = x; ti[TOPK - 1] = e;
                    #pragma unroll
                    for (int jj = TOPK - 1; jj > 0; --jj) {
                        if (tv[jj] > tv[jj - 1]) {
                            float tf = tv[jj]; tv[jj] = tv[jj - 1]; tv[jj - 1] = tf;
                            int   tt = ti[jj]; ti[jj] = ti[jj - 1]; ti[jj - 1] = tt;
                        }
                    }
                }
            }
        }

        const float inv = 1.0f / ((s0 + s1) + (s2 + s3));
        float sc[TOPK];
        #pragma unroll
        for (int k = 0; k < TOPK; ++k) {
            sc[k] = __expf(tv[k]) * inv;
            sh_e[tid * TOPK + k] = (uint8_t)ti[k];
        }
        float4* srow = (float4*)(out_scores + (size_t)t * TOPK);
        srow[0] = make_float4(sc[0], sc[1], sc[2], sc[3]);
        srow[1] = make_float4(sc[4], sc[5], sc[6], sc[7]);
    }

    // init for ranking phase
    if (tid < E_EXPERTS) sh_running[tid] = 0;
    sh_wh[tid] = 0; sh_wh[tid + BLOCK_A] = 0;
    __syncthreads();

    // -------- Phase 2: ordered multisplit ranking over 2048 slots --------
    const size_t slot_base = (size_t)chunk * SLOTS_PER_CHUNK;
    const unsigned lanemask_lt = (1u << lane) - 1u;
    #pragma unroll
    for (int r = 0; r < ROUNDS; ++r) {
        const int slot = r * BLOCK_A + tid;         // token-major slot order
        const int e = sh_e[slot];

        unsigned mask = __match_any_sync(0xffffffffu, e);
        const int lrank = __popc(mask & lanemask_lt);
        const int leader = __ffs(mask) - 1;
        if (lane == leader) sh_wh[warp * E_EXPERTS + e] = __popc(mask);
        __syncthreads();

        // hoisted cross-warp scan: one thread per expert
        if (tid < E_EXPERTS) {
            int run = sh_running[tid];
            #pragma unroll
            for (int w = 0; w < 8; ++w) {
                sh_base[w * E_EXPERTS + tid] = run;
                run += sh_wh[w * E_EXPERTS + tid];
                sh_wh[w * E_EXPERTS + tid] = 0;     // zero for next round
            }
            sh_running[tid] = run;
        }
        __syncthreads();

        const int rank = sh_base[warp * E_EXPERTS + e] + lrank;   // < 256
        g_pack[slot_base + slot] = (uint16_t)((e << 8) | rank);
    }

    if (tid < E_EXPERTS)
        g_chunk_hist[chunk * E_EXPERTS + tid] = sh_running[tid];
}

// ---------------------------------------------------------------------------
// Kernel B: per-expert exclusive scan over 2048 chunk histograms (2 per thread)
// ---------------------------------------------------------------------------
__global__ void scan_kernel(float* __restrict__ out_counts, int n_chunks)
{
    __shared__ int s[1024];
    const int e = blockIdx.x;
    const int c = threadIdx.x;

    const int c0 = 2 * c, c1 = 2 * c + 1;
    int a = (c0 < n_chunks) ? g_chunk_hist[c0 * E_EXPERTS + e] : 0;
    int b = (c1 < n_chunks) ? g_chunk_hist[c1 * E_EXPERTS + e] : 0;
    int pair = a + b;
    s[c] = pair;
    __syncthreads();

    #pragma unroll
    for (int off = 1; off < 1024; off <<= 1) {
        int t = (c >= off) ? s[c - off] : 0;
        __syncthreads();
        s[c] += t;
        __syncthreads();
    }
    const int incl = s[c];
    const int excl = incl - pair;
    if (c0 < n_chunks) g_chunk_base[c0 * E_EXPERTS + e] = excl;
    if (c1 < n_chunks) g_chunk_base[c1 * E_EXPERTS + e] = excl + a;
    if (c == 1023) out_counts[e] = (float)incl;
}

// ---------------------------------------------------------------------------
// Kernel C: final offsets + assignments   (4 slots / thread)
// ---------------------------------------------------------------------------
__global__ __launch_bounds__(256, 8)
void offsets_kernel(float* __restrict__ out_offs,
                    float* __restrict__ out_assign, int n_quads)
{
    const int q = blockIdx.x * blockDim.x + threadIdx.x;
    if (q >= n_quads) return;
    const int idx = q * 4;
    const int chunk = idx >> 11;                    // / SLOTS_PER_CHUNK

    ushort4 p4 = *(const ushort4*)(g_pack + idx);
    const int* base = g_chunk_base + chunk * E_EXPERTS;

    float4 o, a;
    o.x = (float)(base[p4.x >> 8] + (p4.x & 255));  a.x = (float)(p4.x >> 8);
    o.y = (float)(base[p4.y >> 8] + (p4.y & 255));  a.y = (float)(p4.y >> 8);
    o.z = (float)(base[p4.z >> 8] + (p4.z & 255));  a.z = (float)(p4.z >> 8);
    o.w = (float)(base[p4.w >> 8] + (p4.w & 255));  a.w = (float)(p4.w >> 8);
    *(float4*)(out_offs + idx)   = o;
    *(float4*)(out_assign + idx) = a;
}

// ---------------------------------------------------------------------------
extern "C" void kernel_launch(void* const* d_in, const int* in_sizes, int n_in,
                              void* d_out, int out_size)
{
    // inputs: [0]=expert_counts(E), [1]=assignments(N*K), [2]=offsets(N*K), [3]=logits(N*E)
    const float* logits = (const float*)d_in[3];
    const int n_tokens = in_sizes[3] / E_EXPERTS;       // 524288
    const int n_slots  = n_tokens * TOPK;               // 4194304
    const int n_chunks = n_tokens / TOK_PER_BLOCK;      // 2048

    float* out = (float*)d_out;
    // layout: counts[E] | scores[N*K] | assign[N*K] | offs[N*K] | logits[N*E]
    float* out_counts = out;
    float* out_scores = out + E_EXPERTS;
    float* out_assign = out_scores + (size_t)n_slots;
    float* out_offs   = out_assign + (size_t)n_slots;
    float* out_logits = out_offs   + (size_t)n_slots;

    topk_rank_kernel<<<n_chunks, BLOCK_A>>>(logits, out_scores,
                                            out_logits, n_tokens);
    scan_kernel<<<E_EXPERTS, 1024>>>(out_counts, n_chunks);
    const int n_quads = n_slots / 4;
    offsets_kernel<<<(n_quads + 255) / 256, 256>>>(out_offs, out_assign, n_quads);
}

// round 7
// speedup vs baseline: 1.4272x; 1.1795x over previous
#include <cuda_runtime.h>
#include <cuda_bf16.h>
#include <cstdint>
#include <float.h>

// Problem constants (RaggedTopKGatingModule: N=524288, E=64, K=8)
#define E_EXPERTS 64
#define TOPK 8
#define BLOCK_A 256
#define TOK_PER_BLOCK 128                              // 2 lanes per token
#define SLOTS_PER_CHUNK (TOK_PER_BLOCK * TOPK)         // 1024
#define ROUNDS (SLOTS_PER_CHUNK / BLOCK_A)             // 4
#define MAX_SLOTS (524288 * 8)
#define MAX_CHUNKS 4096

// Scratch (no allocation allowed; __device__ globals)
// packed per-slot: (expert_id << 8) | within_chunk_rank   (rank <= 128)
__device__ uint16_t g_pack[MAX_SLOTS];                 // 8 MB
__device__ int      g_chunk_hist[MAX_CHUNKS * E_EXPERTS];
__device__ int      g_chunk_base[MAX_CHUNKS * E_EXPERTS];

// float -> order-preserving uint32 (monotonic, lossless)
__device__ __forceinline__ unsigned f2key(float x) {
    unsigned b = __float_as_uint(x);
    return (b & 0x80000000u) ? ~b : (b | 0x80000000u);
}
__device__ __forceinline__ float key2f(unsigned u) {
    unsigned b = (u & 0x80000000u) ? (u & 0x7fffffffu) : ~u;
    return __uint_as_float(b);
}

// ---------------------------------------------------------------------------
// Kernel A: pair-split exact top-8 + softmax (no max-sub) + logits copy
//           + ordered in-chunk ranking
// ---------------------------------------------------------------------------
__global__ __launch_bounds__(BLOCK_A, 6)
void topk_rank_kernel(const float* __restrict__ logits,
                      float* __restrict__ out_scores,
                      float* __restrict__ out_logits,
                      int n_tokens)
{
    __shared__ unsigned sh_mk[TOK_PER_BLOCK * 16];  // 8 KB  merge keys
    __shared__ uint8_t  sh_me[TOK_PER_BLOCK * 16];  // 2 KB  merge eids
    __shared__ uint8_t  sh_e[SLOTS_PER_CHUNK];      // 1 KB
    __shared__ int sh_wh[8 * E_EXPERTS];            // 2 KB per-warp hist
    __shared__ int sh_base[8 * E_EXPERTS];          // 2 KB scanned bases
    __shared__ int sh_running[E_EXPERTS];           // 256 B

    const int tid  = threadIdx.x;
    const int lane = tid & 31;
    const int warp = tid >> 5;
    const int chunk = blockIdx.x;
    const int tok_base = chunk * TOK_PER_BLOCK;

    // -------- Phase 0: coalesced pass-through copy --------
    {
        const size_t base = (size_t)tok_base * E_EXPERTS;
        const float4* src = (const float4*)(logits + base);
        float4*       dst = (float4*)(out_logits + base);
        const int n4 = TOK_PER_BLOCK * E_EXPERTS / 4;   // 2048 float4
        #pragma unroll
        for (int i = tid; i < n4; i += BLOCK_A)
            dst[i] = src[i];
    }

    // -------- Phase 1: pair-split exact top-8 + softmax --------
    {
        const int lt   = tid >> 1;          // local token 0..127
        const int half = tid & 1;           // 0: experts 0-31, 1: experts 32-63
        const int t = tok_base + lt;
        const float4* row =
            (const float4*)(logits + (size_t)t * E_EXPERTS + half * 32);

        unsigned tv[TOPK];
        int      ti[TOPK];
        #pragma unroll
        for (int k = 0; k < TOPK; ++k) { tv[k] = 0u; ti[k] = 0; }

        float s0 = 0.f, s1 = 0.f, s2 = 0.f, s3 = 0.f;

        #pragma unroll
        for (int j = 0; j < 8; ++j) {       // 32 experts per lane
            float4 q = row[j];
            float xs[4] = {q.x, q.y, q.z, q.w};
            s0 += __expf(q.x); s1 += __expf(q.y);
            s2 += __expf(q.z); s3 += __expf(q.w);
            #pragma unroll
            for (int u = 0; u < 4; ++u) {
                const int le = j * 4 + u;   // local expert id
                const unsigned key = f2key(xs[u]);
                // strict >: lowest-index-first on exact ties within half
                if (key > tv[TOPK - 1]) {
                    tv[TOPK - 1] = key; ti[TOPK - 1] = le;
                    #pragma unroll
                    for (int jj = TOPK - 1; jj > 0; --jj) {
                        if (tv[jj] > tv[jj - 1]) {
                            unsigned tk = tv[jj]; tv[jj] = tv[jj - 1]; tv[jj - 1] = tk;
                            int      tt = ti[jj]; ti[jj] = ti[jj - 1]; ti[jj - 1] = tt;
                        }
                    }
                }
            }
        }

        // publish local top-8 for the pair merge
        const int mbase = lt * 16 + half * 8;
        #pragma unroll
        for (int k = 0; k < TOPK; ++k) {
            sh_mk[mbase + k] = tv[k];
            sh_me[mbase + k] = (uint8_t)(half * 32 + ti[k]);
        }

        const float mysum = (s0 + s1) + (s2 + s3);
        const float total = mysum + __shfl_xor_sync(0xffffffffu, mysum, 1);
        __syncwarp();                       // STS visible across the pair

        if (!half) {
            const unsigned* K   = sh_mk + lt * 16;
            const uint8_t*  Eid = sh_me + lt * 16;
            const float inv = 1.0f / total;

            float sc[TOPK];
            int i = 0, j = 0;
            #pragma unroll
            for (int k = 0; k < TOPK; ++k) {
                unsigned ka = (i < 8) ? K[i] : 0u;
                unsigned kb = (j < 8) ? K[8 + j] : 0u;
                // ties -> even half (experts 0-31) = lower index first
                const bool takeA = (ka >= kb);
                const unsigned kk = takeA ? ka : kb;
                const uint8_t  ee = takeA ? Eid[i] : Eid[8 + j];
                i += takeA; j += !takeA;
                sc[k] = __expf(key2f(kk)) * inv;
                sh_e[lt * TOPK + k] = ee;
            }
            float4* srow = (float4*)(out_scores + (size_t)t * TOPK);
            srow[0] = make_float4(sc[0], sc[1], sc[2], sc[3]);
            srow[1] = make_float4(sc[4], sc[5], sc[6], sc[7]);
        }
    }

    // init for ranking phase
    if (tid < E_EXPERTS) sh_running[tid] = 0;
    sh_wh[tid] = 0; sh_wh[tid + BLOCK_A] = 0;
    __syncthreads();

    // -------- Phase 2: ordered multisplit ranking over 1024 slots --------
    const size_t slot_base = (size_t)chunk * SLOTS_PER_CHUNK;
    const unsigned lanemask_lt = (1u << lane) - 1u;
    #pragma unroll
    for (int r = 0; r < ROUNDS; ++r) {
        const int slot = r * BLOCK_A + tid;         // token-major slot order
        const int e = sh_e[slot];

        unsigned mask = __match_any_sync(0xffffffffu, e);
        const int lrank = __popc(mask & lanemask_lt);
        const int leader = __ffs(mask) - 1;
        if (lane == leader) sh_wh[warp * E_EXPERTS + e] = __popc(mask);
        __syncthreads();

        // hoisted cross-warp scan: one thread per expert
        if (tid < E_EXPERTS) {
            int run = sh_running[tid];
            #pragma unroll
            for (int w = 0; w < 8; ++w) {
                sh_base[w * E_EXPERTS + tid] = run;
                run += sh_wh[w * E_EXPERTS + tid];
                sh_wh[w * E_EXPERTS + tid] = 0;     // zero for next round
            }
            sh_running[tid] = run;
        }
        __syncthreads();

        const int rank = sh_base[warp * E_EXPERTS + e] + lrank;   // <= 128
        g_pack[slot_base + slot] = (uint16_t)((e << 8) | rank);
    }

    if (tid < E_EXPERTS)
        g_chunk_hist[chunk * E_EXPERTS + tid] = sh_running[tid];
}

// ---------------------------------------------------------------------------
// Kernel B: per-expert exclusive scan over 4096 chunk histograms (4 per thread)
// ---------------------------------------------------------------------------
__global__ void scan_kernel(float* __restrict__ out_counts, int n_chunks)
{
    __shared__ int s[1024];
    const int e = blockIdx.x;
    const int c = threadIdx.x;

    int v[4];
    #pragma unroll
    for (int i = 0; i < 4; ++i) {
        const int ci = 4 * c + i;
        v[i] = (ci < n_chunks) ? g_chunk_hist[ci * E_EXPERTS + e] : 0;
    }
    const int quad = v[0] + v[1] + v[2] + v[3];
    s[c] = quad;
    __syncthreads();

    #pragma unroll
    for (int off = 1; off < 1024; off <<= 1) {
        int t = (c >= off) ? s[c - off] : 0;
        __syncthreads();
        s[c] += t;
        __syncthreads();
    }
    const int incl = s[c];
    int run = incl - quad;
    #pragma unroll
    for (int i = 0; i < 4; ++i) {
        const int ci = 4 * c + i;
        if (ci < n_chunks) g_chunk_base[ci * E_EXPERTS + e] = run;
        run += v[i];
    }
    if (c == 1023) out_counts[e] = (float)incl;
}

// ---------------------------------------------------------------------------
// Kernel C: final offsets + assignments   (4 slots / thread)
// ---------------------------------------------------------------------------
__global__ __launch_bounds__(256, 8)
void offsets_kernel(float* __restrict__ out_offs,
                    float* __restrict__ out_assign, int n_quads)
{
    const int q = blockIdx.x * blockDim.x + threadIdx.x;
    if (q >= n_quads) return;
    const int idx = q * 4;
    const int chunk = idx >> 10;                    // / SLOTS_PER_CHUNK (1024)

    ushort4 p4 = *(const ushort4*)(g_pack + idx);
    const int* base = g_chunk_base + chunk * E_EXPERTS;

    float4 o, a;
    o.x = (float)(base[p4.x >> 8] + (p4.x & 255));  a.x = (float)(p4.x >> 8);
    o.y = (float)(base[p4.y >> 8] + (p4.y & 255));  a.y = (float)(p4.y >> 8);
    o.z = (float)(base[p4.z >> 8] + (p4.z & 255));  a.z = (float)(p4.z >> 8);
    o.w = (float)(base[p4.w >> 8] + (p4.w & 255));  a.w = (float)(p4.w >> 8);
    *(float4*)(out_offs + idx)   = o;
    *(float4*)(out_assign + idx) = a;
}

// ---------------------------------------------------------------------------
extern "C" void kernel_launch(void* const* d_in, const int* in_sizes, int n_in,
                              void* d_out, int out_size)
{
    // inputs: [0]=expert_counts(E), [1]=assignments(N*K), [2]=offsets(N*K), [3]=logits(N*E)
    const float* logits = (const float*)d_in[3];
    const int n_tokens = in_sizes[3] / E_EXPERTS;       // 524288
    const int n_slots  = n_tokens * TOPK;               // 4194304
    const int n_chunks = n_tokens / TOK_PER_BLOCK;      // 4096

    float* out = (float*)d_out;
    // layout: counts[E] | scores[N*K] | assign[N*K] | offs[N*K] | logits[N*E]
    float* out_counts = out;
    float* out_scores = out + E_EXPERTS;
    float* out_assign = out_scores + (size_t)n_slots;
    float* out_offs   = out_assign + (size_t)n_slots;
    float* out_logits = out_offs   + (size_t)n_slots;

    topk_rank_kernel<<<n_chunks, BLOCK_A>>>(logits, out_scores,
                                            out_logits, n_tokens);
    scan_kernel<<<E_EXPERTS, 1024>>>(out_counts, n_chunks);
    const int n_quads = n_slots / 4;
    offsets_kernel<<<(n_quads + 255) / 256, 256>>>(out_offs, out_assign, n_quads);
}